// round 3
// baseline (speedup 1.0000x reference)
#include <cuda_runtime.h>

#define D   16
#define LIB 969
#define TPB 128
#define RPT 4                      // batch rows per thread
#define ROWS_PER_BLOCK (RPT * TPB) // 512

__device__ float g_masked[LIB * D];   // masked coefficients (prep kernel fills)

// packed fp32x2 FMA: acc = m * c + acc
#define FFMA2(acc, m, c) \
    asm("fma.rn.f32x2 %0, %1, %2, %0;" : "+l"(acc) : "l"(m), "l"(c))
// packed fp32x2 MUL
#define MULX2(dst, a, b) \
    asm("mul.rn.f32x2 %0, %1, %2;" : "=l"(dst) : "l"(a), "l"(b))
// unpack b64 -> two u32
#define UNPK(lo, hi, p) \
    asm("mov.b64 {%0, %1}, %2;" : "=r"(lo), "=r"(hi) : "l"(p))
// splat u32 -> b64
#define SPLAT(dst, s) \
    asm("mov.b64 %0, {%1, %1};" : "=l"(dst) : "r"(s))

__global__ void prep_kernel(const float* __restrict__ coeff,
                            const float* __restrict__ fixedv,
                            const unsigned char* __restrict__ fmask)
{
    int i = blockIdx.x * blockDim.x + threadIdx.x;
    if (i < LIB * D) g_masked[i] = fmask[i] ? fixedv[i] : coeff[i];
}

__global__ __launch_bounds__(TPB, 5) void sindy_kernel(
    const float* __restrict__ z,
    float* __restrict__ out,
    int B)
{
    // packed (z_r0, z_r1) and (z_r2, z_r3) per dim, layout [k][tid]
    __shared__ unsigned long long zs01[D * TPB];
    __shared__ unsigned long long zs23[D * TPB];

    const int tid = threadIdx.x;

    const long r0 = (long)blockIdx.x * ROWS_PER_BLOCK + tid;
    const long r1 = r0 + TPB;
    const long r2 = r0 + 2 * TPB;
    const long r3 = r0 + 3 * TPB;
    const bool v0 = r0 < B, v1 = r1 < B, v2 = r2 < B, v3 = r3 < B;

    // Load 4 z rows, zero-fill invalid, pack pairs into smem
    {
        const float4* p0 = (const float4*)(z + r0 * D);
        const float4* p1 = (const float4*)(z + r1 * D);
        const float4* p2 = (const float4*)(z + r2 * D);
        const float4* p3 = (const float4*)(z + r3 * D);
#pragma unroll
        for (int q = 0; q < 4; q++) {
            float4 t0 = v0 ? p0[q] : make_float4(0.f,0.f,0.f,0.f);
            float4 t1 = v1 ? p1[q] : make_float4(0.f,0.f,0.f,0.f);
            float4 t2 = v2 ? p2[q] : make_float4(0.f,0.f,0.f,0.f);
            float4 t3 = v3 ? p3[q] : make_float4(0.f,0.f,0.f,0.f);
            float a0[4] = {t0.x,t0.y,t0.z,t0.w};
            float a1[4] = {t1.x,t1.y,t1.z,t1.w};
            float a2[4] = {t2.x,t2.y,t2.z,t2.w};
            float a3[4] = {t3.x,t3.y,t3.z,t3.w};
#pragma unroll
            for (int s = 0; s < 4; s++) {
                unsigned long long p01, p23;
                asm("mov.b64 %0, {%1, %2};" : "=l"(p01)
                    : "r"(__float_as_uint(a0[s])), "r"(__float_as_uint(a1[s])));
                asm("mov.b64 %0, {%1, %2};" : "=l"(p23)
                    : "r"(__float_as_uint(a2[s])), "r"(__float_as_uint(a3[s])));
                zs01[(4*q+s) * TPB + tid] = p01;
                zs23[(4*q+s) * TPB + tid] = p23;
            }
        }
    }
    __syncthreads();

    // Coefficient stream: 969 rows x 16 floats = 969 x (4 x ulonglong2)
    const ulonglong2* cp = (const ulonglong2*)g_masked;

    // 8 packed accumulators per batch row; init = constant-term coeff row
    unsigned long long a0[8], a1[8], a2[8], a3[8];
    {
        ulonglong2 i0 = __ldg(cp + 0);
        ulonglong2 i1 = __ldg(cp + 1);
        ulonglong2 i2 = __ldg(cp + 2);
        ulonglong2 i3 = __ldg(cp + 3);
        a0[0]=i0.x; a0[1]=i0.y; a0[2]=i1.x; a0[3]=i1.y;
        a0[4]=i2.x; a0[5]=i2.y; a0[6]=i3.x; a0[7]=i3.y;
#pragma unroll
        for (int p = 0; p < 8; p++) { a1[p]=a0[p]; a2[p]=a0[p]; a3[p]=a0[p]; }
    }
    cp += 4;

    // Prefetched coefficient row registers
    ulonglong2 q0 = __ldg(cp + 0), q1 = __ldg(cp + 1),
               q2 = __ldg(cp + 2), q3 = __ldg(cp + 3);
    cp += 4;

    // One coefficient row: issue next row's loads, splat monomials, 32 FFMA2
#define ROW(mp01, mp23) do {                                                \
        ulonglong2 n0 = __ldg(cp + 0);                                      \
        ulonglong2 n1 = __ldg(cp + 1);                                      \
        ulonglong2 n2 = __ldg(cp + 2);                                      \
        ulonglong2 n3 = __ldg(cp + 3);                                      \
        cp += 4;                                                            \
        unsigned u0_, u1_, u2_, u3_;                                        \
        unsigned long long s0_, s1_, s2_, s3_;                              \
        UNPK(u0_, u1_, (mp01)); UNPK(u2_, u3_, (mp23));                     \
        SPLAT(s0_, u0_); SPLAT(s1_, u1_); SPLAT(s2_, u2_); SPLAT(s3_, u3_); \
        FFMA2(a0[0], s0_, q0.x); FFMA2(a1[0], s1_, q0.x);                   \
        FFMA2(a2[0], s2_, q0.x); FFMA2(a3[0], s3_, q0.x);                   \
        FFMA2(a0[1], s0_, q0.y); FFMA2(a1[1], s1_, q0.y);                   \
        FFMA2(a2[1], s2_, q0.y); FFMA2(a3[1], s3_, q0.y);                   \
        FFMA2(a0[2], s0_, q1.x); FFMA2(a1[2], s1_, q1.x);                   \
        FFMA2(a2[2], s2_, q1.x); FFMA2(a3[2], s3_, q1.x);                   \
        FFMA2(a0[3], s0_, q1.y); FFMA2(a1[3], s1_, q1.y);                   \
        FFMA2(a2[3], s2_, q1.y); FFMA2(a3[3], s3_, q1.y);                   \
        FFMA2(a0[4], s0_, q2.x); FFMA2(a1[4], s1_, q2.x);                   \
        FFMA2(a2[4], s2_, q2.x); FFMA2(a3[4], s3_, q2.x);                   \
        FFMA2(a0[5], s0_, q2.y); FFMA2(a1[5], s1_, q2.y);                   \
        FFMA2(a2[5], s2_, q2.y); FFMA2(a3[5], s3_, q2.y);                   \
        FFMA2(a0[6], s0_, q3.x); FFMA2(a1[6], s1_, q3.x);                   \
        FFMA2(a2[6], s2_, q3.x); FFMA2(a3[6], s3_, q3.x);                   \
        FFMA2(a0[7], s0_, q3.y); FFMA2(a1[7], s1_, q3.y);                   \
        FFMA2(a2[7], s2_, q3.y); FFMA2(a3[7], s3_, q3.y);                   \
        q0 = n0; q1 = n1; q2 = n2; q3 = n3;                                 \
    } while (0)

    // ---- order 1: z_i ----
#pragma unroll 1
    for (int i = 0; i < D; i++) {
        unsigned long long m01 = zs01[i * TPB + tid];
        unsigned long long m23 = zs23[i * TPB + tid];
        ROW(m01, m23);
    }
    // ---- order 2: z_i * z_j, i<=j ----
#pragma unroll 1
    for (int i = 0; i < D; i++) {
        unsigned long long zi01 = zs01[i * TPB + tid];
        unsigned long long zi23 = zs23[i * TPB + tid];
#pragma unroll 1
        for (int j = i; j < D; j++) {
            unsigned long long m01, m23;
            MULX2(m01, zi01, zs01[j * TPB + tid]);
            MULX2(m23, zi23, zs23[j * TPB + tid]);
            ROW(m01, m23);
        }
    }
    // ---- order 3: z_i * z_j * z_k, i<=j<=k ----
#pragma unroll 1
    for (int i = 0; i < D; i++) {
        unsigned long long zi01 = zs01[i * TPB + tid];
        unsigned long long zi23 = zs23[i * TPB + tid];
#pragma unroll 1
        for (int j = i; j < D; j++) {
            unsigned long long pp01, pp23;
            MULX2(pp01, zi01, zs01[j * TPB + tid]);
            MULX2(pp23, zi23, zs23[j * TPB + tid]);
#pragma unroll 1
            for (int k = j; k < D; k++) {
                unsigned long long m01, m23;
                MULX2(m01, pp01, zs01[k * TPB + tid]);
                MULX2(m23, pp23, zs23[k * TPB + tid]);
                ROW(m01, m23);
            }
        }
    }
#undef ROW

    // Store 16 fp32 outputs per valid row
    if (v0) {
        ulonglong2* o = (ulonglong2*)(out + r0 * D);
        o[0] = make_ulonglong2(a0[0], a0[1]); o[1] = make_ulonglong2(a0[2], a0[3]);
        o[2] = make_ulonglong2(a0[4], a0[5]); o[3] = make_ulonglong2(a0[6], a0[7]);
    }
    if (v1) {
        ulonglong2* o = (ulonglong2*)(out + r1 * D);
        o[0] = make_ulonglong2(a1[0], a1[1]); o[1] = make_ulonglong2(a1[2], a1[3]);
        o[2] = make_ulonglong2(a1[4], a1[5]); o[3] = make_ulonglong2(a1[6], a1[7]);
    }
    if (v2) {
        ulonglong2* o = (ulonglong2*)(out + r2 * D);
        o[0] = make_ulonglong2(a2[0], a2[1]); o[1] = make_ulonglong2(a2[2], a2[3]);
        o[2] = make_ulonglong2(a2[4], a2[5]); o[3] = make_ulonglong2(a2[6], a2[7]);
    }
    if (v3) {
        ulonglong2* o = (ulonglong2*)(out + r3 * D);
        o[0] = make_ulonglong2(a3[0], a3[1]); o[1] = make_ulonglong2(a3[2], a3[3]);
        o[2] = make_ulonglong2(a3[4], a3[5]); o[3] = make_ulonglong2(a3[6], a3[7]);
    }
}

extern "C" void kernel_launch(void* const* d_in, const int* in_sizes, int n_in,
                              void* d_out, int out_size)
{
    const float*         z      = (const float*)d_in[0];
    const float*         coeff  = (const float*)d_in[1];
    const float*         fixedv = (const float*)d_in[2];
    const unsigned char* fmask  = (const unsigned char*)d_in[3];
    float*               out    = (float*)d_out;

    const int B = in_sizes[0] / D;

    prep_kernel<<<(LIB * D + 255) / 256, 256>>>(coeff, fixedv, fmask);

    const int grid = (B + ROWS_PER_BLOCK - 1) / ROWS_PER_BLOCK;
    sindy_kernel<<<grid, TPB>>>(z, out, B);
}

// round 4
// speedup vs baseline: 1.7910x; 1.7910x over previous
#include <cuda_runtime.h>

#define D   16
#define LIB 969
#define TPB 128
#define RPT 4
#define ROWS_PER_BLOCK (RPT * TPB)   // 512

__constant__ float c_coeff[LIB * D];   // masked coefficients (62016 B)

// packed fp32x2 FMA: acc = m * c + acc
#define FFMA2(acc, m, c) \
    asm("fma.rn.f32x2 %0, %1, %2, %0;" : "+l"(acc) : "l"(m), "l"(c))
// packed fp32x2 MUL
#define MULX2(dst, a, b) \
    asm("mul.rn.f32x2 %0, %1, %2;" : "=l"(dst) : "l"(a), "l"(b))
// unpack b64 -> two u32
#define UNPK(lo, hi, p) \
    asm("mov.b64 {%0, %1}, %2;" : "=r"(lo), "=r"(hi) : "l"(p))
// splat u32 -> b64
#define SPLAT(dst, s) \
    asm("mov.b64 %0, {%1, %1};" : "=l"(dst) : "r"(s))

// 128-bit load from constant space (dedicated constant port, not L1tex)
__device__ __forceinline__ ulonglong2 ldc_v2(unsigned long long caddr) {
    ulonglong2 r;
    asm("ld.const.v2.u64 {%0, %1}, [%2];" : "=l"(r.x), "=l"(r.y) : "l"(caddr));
    return r;
}

// Writes masked coefficients directly into c_coeff's backing store (global
// write -> next launch reads via constant port; launch-boundary flush makes
// this coherent, same as the D2D-memcpy path validated in round 2).
__global__ void prep_kernel(const float* __restrict__ coeff,
                            const float* __restrict__ fixedv,
                            const unsigned char* __restrict__ fmask,
                            float* __restrict__ cdst)
{
    int i = blockIdx.x * blockDim.x + threadIdx.x;
    if (i < LIB * D) cdst[i] = fmask[i] ? fixedv[i] : coeff[i];
}

__global__ __launch_bounds__(TPB, 5) void sindy_kernel(
    const float* __restrict__ z,
    float* __restrict__ out,
    int B)
{
    // packed (z_r0,z_r1) and (z_r2,z_r3) per dim, layout [k][tid]
    __shared__ unsigned long long zs01[D * TPB];
    __shared__ unsigned long long zs23[D * TPB];

    const int tid = threadIdx.x;

    unsigned long long cbase;
    asm("mov.u64 %0, c_coeff;" : "=l"(cbase));

    const long r0 = (long)blockIdx.x * ROWS_PER_BLOCK + tid;
    const long r1 = r0 + TPB;
    const long r2 = r0 + 2 * TPB;
    const long r3 = r0 + 3 * TPB;
    const bool v0 = r0 < B, v1 = r1 < B, v2 = r2 < B, v3 = r3 < B;

    // Load 4 z rows (float4 x4 each), zero-fill invalid, pack pairs into smem
    {
        const float4* p0 = (const float4*)(z + r0 * D);
        const float4* p1 = (const float4*)(z + r1 * D);
        const float4* p2 = (const float4*)(z + r2 * D);
        const float4* p3 = (const float4*)(z + r3 * D);
#pragma unroll
        for (int q = 0; q < 4; q++) {
            float4 t0 = v0 ? p0[q] : make_float4(0.f,0.f,0.f,0.f);
            float4 t1 = v1 ? p1[q] : make_float4(0.f,0.f,0.f,0.f);
            float4 t2 = v2 ? p2[q] : make_float4(0.f,0.f,0.f,0.f);
            float4 t3 = v3 ? p3[q] : make_float4(0.f,0.f,0.f,0.f);
            float a0[4] = {t0.x,t0.y,t0.z,t0.w};
            float a1[4] = {t1.x,t1.y,t1.z,t1.w};
            float a2[4] = {t2.x,t2.y,t2.z,t2.w};
            float a3[4] = {t3.x,t3.y,t3.z,t3.w};
#pragma unroll
            for (int s = 0; s < 4; s++) {
                unsigned long long p01, p23;
                asm("mov.b64 %0, {%1, %2};" : "=l"(p01)
                    : "r"(__float_as_uint(a0[s])), "r"(__float_as_uint(a1[s])));
                asm("mov.b64 %0, {%1, %2};" : "=l"(p23)
                    : "r"(__float_as_uint(a2[s])), "r"(__float_as_uint(a3[s])));
                zs01[(4*q+s) * TPB + tid] = p01;
                zs23[(4*q+s) * TPB + tid] = p23;
            }
        }
    }
    __syncthreads();

    // 8 packed accumulators per pair; init = constant-term coeff row
    unsigned long long a0[8], a1[8], a2[8], a3[8];
    {
        ulonglong2 i0 = ldc_v2(cbase +  0);
        ulonglong2 i1 = ldc_v2(cbase + 16);
        ulonglong2 i2 = ldc_v2(cbase + 32);
        ulonglong2 i3 = ldc_v2(cbase + 48);
        a0[0]=i0.x; a0[1]=i0.y; a0[2]=i1.x; a0[3]=i1.y;
        a0[4]=i2.x; a0[5]=i2.y; a0[6]=i3.x; a0[7]=i3.y;
#pragma unroll
        for (int p = 0; p < 8; p++) { a1[p]=a0[p]; a2[p]=a0[p]; a3[p]=a0[p]; }
    }
    unsigned long long cptr = cbase + 64;

    // One coefficient row: 4x LDC.128 + splats + 32 FFMA2 (4 batch rows)
#define ROW(mp01, mp23) do {                                                \
        unsigned u0_, u1_, u2_, u3_;                                        \
        unsigned long long s0_, s1_, s2_, s3_;                              \
        UNPK(u0_, u1_, (mp01)); UNPK(u2_, u3_, (mp23));                     \
        SPLAT(s0_, u0_); SPLAT(s1_, u1_); SPLAT(s2_, u2_); SPLAT(s3_, u3_); \
        ulonglong2 q0 = ldc_v2(cptr +  0);                                  \
        ulonglong2 q1 = ldc_v2(cptr + 16);                                  \
        ulonglong2 q2 = ldc_v2(cptr + 32);                                  \
        ulonglong2 q3 = ldc_v2(cptr + 48);                                  \
        FFMA2(a0[0], s0_, q0.x); FFMA2(a1[0], s1_, q0.x);                   \
        FFMA2(a2[0], s2_, q0.x); FFMA2(a3[0], s3_, q0.x);                   \
        FFMA2(a0[1], s0_, q0.y); FFMA2(a1[1], s1_, q0.y);                   \
        FFMA2(a2[1], s2_, q0.y); FFMA2(a3[1], s3_, q0.y);                   \
        FFMA2(a0[2], s0_, q1.x); FFMA2(a1[2], s1_, q1.x);                   \
        FFMA2(a2[2], s2_, q1.x); FFMA2(a3[2], s3_, q1.x);                   \
        FFMA2(a0[3], s0_, q1.y); FFMA2(a1[3], s1_, q1.y);                   \
        FFMA2(a2[3], s2_, q1.y); FFMA2(a3[3], s3_, q1.y);                   \
        FFMA2(a0[4], s0_, q2.x); FFMA2(a1[4], s1_, q2.x);                   \
        FFMA2(a2[4], s2_, q2.x); FFMA2(a3[4], s3_, q2.x);                   \
        FFMA2(a0[5], s0_, q2.y); FFMA2(a1[5], s1_, q2.y);                   \
        FFMA2(a2[5], s2_, q2.y); FFMA2(a3[5], s3_, q2.y);                   \
        FFMA2(a0[6], s0_, q3.x); FFMA2(a1[6], s1_, q3.x);                   \
        FFMA2(a2[6], s2_, q3.x); FFMA2(a3[6], s3_, q3.x);                   \
        FFMA2(a0[7], s0_, q3.y); FFMA2(a1[7], s1_, q3.y);                   \
        FFMA2(a2[7], s2_, q3.y); FFMA2(a3[7], s3_, q3.y);                   \
        cptr += 64;                                                         \
    } while (0)

    // ---- order 1: z_i ----
#pragma unroll 1
    for (int i = 0; i < D; i++) {
        unsigned long long m01 = zs01[i * TPB + tid];
        unsigned long long m23 = zs23[i * TPB + tid];
        ROW(m01, m23);
    }
    // ---- order 2: z_i * z_j, i<=j ----
#pragma unroll 1
    for (int i = 0; i < D; i++) {
        unsigned long long zi01 = zs01[i * TPB + tid];
        unsigned long long zi23 = zs23[i * TPB + tid];
#pragma unroll 1
        for (int j = i; j < D; j++) {
            unsigned long long m01, m23;
            MULX2(m01, zi01, zs01[j * TPB + tid]);
            MULX2(m23, zi23, zs23[j * TPB + tid]);
            ROW(m01, m23);
        }
    }
    // ---- order 3: z_i * z_j * z_k, i<=j<=k ----
#pragma unroll 1
    for (int i = 0; i < D; i++) {
        unsigned long long zi01 = zs01[i * TPB + tid];
        unsigned long long zi23 = zs23[i * TPB + tid];
#pragma unroll 1
        for (int j = i; j < D; j++) {
            unsigned long long pp01, pp23;
            MULX2(pp01, zi01, zs01[j * TPB + tid]);
            MULX2(pp23, zi23, zs23[j * TPB + tid]);
#pragma unroll 1
            for (int k = j; k < D; k++) {
                unsigned long long m01, m23;
                MULX2(m01, pp01, zs01[k * TPB + tid]);
                MULX2(m23, pp23, zs23[k * TPB + tid]);
                ROW(m01, m23);
            }
        }
    }
#undef ROW

    if (v0) {
        ulonglong2* o = (ulonglong2*)(out + r0 * D);
        o[0] = make_ulonglong2(a0[0], a0[1]); o[1] = make_ulonglong2(a0[2], a0[3]);
        o[2] = make_ulonglong2(a0[4], a0[5]); o[3] = make_ulonglong2(a0[6], a0[7]);
    }
    if (v1) {
        ulonglong2* o = (ulonglong2*)(out + r1 * D);
        o[0] = make_ulonglong2(a1[0], a1[1]); o[1] = make_ulonglong2(a1[2], a1[3]);
        o[2] = make_ulonglong2(a1[4], a1[5]); o[3] = make_ulonglong2(a1[6], a1[7]);
    }
    if (v2) {
        ulonglong2* o = (ulonglong2*)(out + r2 * D);
        o[0] = make_ulonglong2(a2[0], a2[1]); o[1] = make_ulonglong2(a2[2], a2[3]);
        o[2] = make_ulonglong2(a2[4], a2[5]); o[3] = make_ulonglong2(a2[6], a2[7]);
    }
    if (v3) {
        ulonglong2* o = (ulonglong2*)(out + r3 * D);
        o[0] = make_ulonglong2(a3[0], a3[1]); o[1] = make_ulonglong2(a3[2], a3[3]);
        o[2] = make_ulonglong2(a3[4], a3[5]); o[3] = make_ulonglong2(a3[6], a3[7]);
    }
}

extern "C" void kernel_launch(void* const* d_in, const int* in_sizes, int n_in,
                              void* d_out, int out_size)
{
    const float*         z      = (const float*)d_in[0];
    const float*         coeff  = (const float*)d_in[1];
    const float*         fixedv = (const float*)d_in[2];
    const unsigned char* fmask  = (const unsigned char*)d_in[3];
    float*               out    = (float*)d_out;

    const int B = in_sizes[0] / D;

    // Device pointer to c_coeff's backing store (queried once per call;
    // not a stream operation, safe under graph capture).
    void* csym = nullptr;
    cudaGetSymbolAddress(&csym, c_coeff);

    prep_kernel<<<(LIB * D + 255) / 256, 256>>>(coeff, fixedv, fmask,
                                                (float*)csym);

    const int grid = (B + ROWS_PER_BLOCK - 1) / ROWS_PER_BLOCK;
    sindy_kernel<<<grid, TPB>>>(z, out, B);
}